// round 4
// baseline (speedup 1.0000x reference)
#include <cuda_runtime.h>
#include <cuda_fp16.h>
#include <math.h>

#define Nn 30000
#define NN0 18000
#define NN1 12000
#define Rr 5
#define Ee 600000
#define Hh 128
#define Cc 8
#define OFF_X (Nn*Cc)            /* 240000   */
#define OFF_U (OFF_X + Nn*Hh)    /* 4080000  */

// ---------------- device scratch (static, no allocation) ----------------
__device__ float  g_h [Nn*Hh];
__device__ float  g_xa[Nn*Hh];
__device__ float  g_xb[Nn*Hh];
__device__ __half g_xh[Nn*Hh];                 // fp16 mirror of current x (7.7 MB)
__device__ __half g_msgh[(size_t)Rr*Nn*Hh];    // per-relation messages fp16 (38.4 MB)
__device__ int    g_degi[Rr*Nn];
__device__ int    g_cnt[Nn];
__device__ int    g_rowptr[Nn+1];
__device__ int    g_cur2[Rr*Nn];
__device__ int    g_bsums[64];
__device__ int    g_csr_dst[Ee];
__device__ float  g_csr_edinv[Ee];
__device__ double g_node[Rr];
__device__ double g_edge[Rr];
__device__ float  g_u[Rr];
__device__ float  g_clt;
__device__ int    g_act;
__device__ int    g_still;
__device__ unsigned g_barrier;

__device__ __forceinline__ float wsum(float v){
    #pragma unroll
    for (int o = 16; o; o >>= 1) v += __shfl_xor_sync(0xffffffffu, v, o);
    return v;
}
__device__ __forceinline__ float n2n(float v){
    if (isnan(v)) return 0.f;
    if (isinf(v)) return v > 0.f ? 3.4028234663852886e38f : -3.4028234663852886e38f;
    return v;
}

// ---------------- init / graph preprocessing ----------------
__global__ void k_init(){
    int i = blockIdx.x*blockDim.x + threadIdx.x;
    int st = gridDim.x*blockDim.x;
    for (int j = i; j < Rr*Nn; j += st) g_degi[j] = 0;
    for (int j = i; j < Nn;    j += st) g_cnt[j]  = 0;
    if (i < Rr) { g_node[i] = 0.0; g_edge[i] = 0.0; g_u[i] = 0.2f; }
    if (i == 0) { g_act = 1; g_still = 1; g_barrier = 0u; }
}

__global__ void k_count(const int* __restrict__ src, const int* __restrict__ rel){
    int i = blockIdx.x*blockDim.x + threadIdx.x;
    if (i < Ee) {
        atomicAdd(&g_degi[rel[i]*Nn + src[i]], 1);
        atomicAdd(&g_cnt[src[i]], 1);
    }
}

__global__ void k_scan1(){
    __shared__ int s[1024];
    int i = blockIdx.x*1024 + threadIdx.x;
    int v = (i < Nn) ? g_cnt[i] : 0;
    s[threadIdx.x] = v;
    __syncthreads();
    for (int off = 1; off < 1024; off <<= 1){
        int t = 0;
        if (threadIdx.x >= off) t = s[threadIdx.x - off];
        __syncthreads();
        if (threadIdx.x >= off) s[threadIdx.x] += t;
        __syncthreads();
    }
    if (i < Nn) g_rowptr[i] = s[threadIdx.x] - v;
    if (threadIdx.x == 1023) g_bsums[blockIdx.x] = s[1023];
}

__global__ void k_scan2(int nb){
    if (threadIdx.x == 0){
        int run = 0;
        for (int b = 0; b < nb; b++){ int t = g_bsums[b]; g_bsums[b] = run; run += t; }
    }
}

__global__ void k_scan3(){
    int i = blockIdx.x*blockDim.x + threadIdx.x;
    if (i < Nn) g_rowptr[i] = g_rowptr[i] + g_bsums[i >> 10];
    if (i == 0) g_rowptr[Nn] = Ee;
}

__global__ void k_cursor2(){
    int s = blockIdx.x*blockDim.x + threadIdx.x;
    if (s >= Nn) return;
    int base = g_rowptr[s];
    #pragma unroll
    for (int r = 0; r < Rr; r++){
        g_cur2[r*Nn + s] = base;
        base += g_degi[r*Nn + s];
    }
}

__global__ void k_scatter2(const int* __restrict__ src, const int* __restrict__ dst,
                           const int* __restrict__ rel){
    int i = blockIdx.x*blockDim.x + threadIdx.x;
    if (i >= Ee) return;
    int s = src[i], r = rel[i], d = dst[i];
    int pos = atomicAdd(&g_cur2[r*Nn + s], 1);
    int degs = g_degi[r*Nn + s];
    int degd = g_degi[r*Nn + d];
    float ei = (1.f/sqrtf((float)degs)) * (degd > 0 ? 1.f/sqrtf((float)degd) : 0.f);
    g_csr_dst[pos]   = d;
    g_csr_edinv[pos] = ei;
}

// ---------------- stage A GEMM: h = feat @ W + b ----------------
__global__ void __launch_bounds__(256) k_gemm(const float* __restrict__ A, int lda, int nrows,
                                              int rowbase,
                                              const float* __restrict__ W,
                                              const float* __restrict__ bias, int K){
    __shared__ float As[64*17];
    __shared__ float Bs[16*128];
    int tid  = threadIdx.x;
    int tcol = tid & 31, trow = tid >> 5;
    int row0 = blockIdx.x * 64;
    float acc[8][4];
    #pragma unroll
    for (int i = 0; i < 8; i++){ acc[i][0]=0.f; acc[i][1]=0.f; acc[i][2]=0.f; acc[i][3]=0.f; }

    for (int k0 = 0; k0 < K; k0 += 16){
        #pragma unroll
        for (int i = 0; i < 4; i++){
            int lin = tid + 256*i;
            int r = lin >> 4, k = lin & 15;
            int gr = row0 + r;
            As[r*17+k] = (gr < nrows) ? A[gr*lda + k0 + k] : 0.f;
        }
        #pragma unroll
        for (int i = 0; i < 8; i++){
            int lin = tid + 256*i;
            int k = lin >> 7, c = lin & 127;
            Bs[k*128+c] = W[(k0+k)*128 + c];
        }
        __syncthreads();
        #pragma unroll
        for (int k = 0; k < 16; k++){
            float4 bv = *(const float4*)&Bs[k*128 + tcol*4];
            #pragma unroll
            for (int ri = 0; ri < 8; ri++){
                float a = As[(trow*8+ri)*17 + k];
                acc[ri][0] += a*bv.x; acc[ri][1] += a*bv.y;
                acc[ri][2] += a*bv.z; acc[ri][3] += a*bv.w;
            }
        }
        __syncthreads();
    }
    float4 bv = *(const float4*)&bias[tcol*4];
    #pragma unroll
    for (int ri = 0; ri < 8; ri++){
        int gr = row0 + trow*8 + ri;
        if (gr < nrows){
            float4 o = make_float4(acc[ri][0]+bv.x, acc[ri][1]+bv.y,
                                   acc[ri][2]+bv.z, acc[ri][3]+bv.w);
            *(float4*)&g_h[(rowbase+gr)*Hh + tcol*4] = o;
        }
    }
}

// ---------------- stage B: LN(h@Wm1+b)->relu -> @Wm2+b -> standardize ----------------
__global__ void __launch_bounds__(256) k_mlp2(const float* __restrict__ Wm1, const float* __restrict__ bm1,
                                              const float* __restrict__ Wm2, const float* __restrict__ bm2){
    __shared__ float As[64*17];
    __shared__ float Bs[16*128];
    __shared__ float Zs[64*132];
    int tid  = threadIdx.x;
    int tcol = tid & 31, trow = tid >> 5;
    int row0 = blockIdx.x * 64;
    float acc[8][4];
    #pragma unroll
    for (int i = 0; i < 8; i++){ acc[i][0]=0.f; acc[i][1]=0.f; acc[i][2]=0.f; acc[i][3]=0.f; }

    for (int k0 = 0; k0 < 128; k0 += 16){
        #pragma unroll
        for (int i = 0; i < 4; i++){
            int lin = tid + 256*i;
            int r = lin >> 4, k = lin & 15;
            int gr = row0 + r;
            As[r*17+k] = (gr < Nn) ? g_h[gr*Hh + k0 + k] : 0.f;
        }
        #pragma unroll
        for (int i = 0; i < 8; i++){
            int lin = tid + 256*i;
            int k = lin >> 7, c = lin & 127;
            Bs[k*128+c] = Wm1[(k0+k)*128 + c];
        }
        __syncthreads();
        #pragma unroll
        for (int k = 0; k < 16; k++){
            float4 bv = *(const float4*)&Bs[k*128 + tcol*4];
            #pragma unroll
            for (int ri = 0; ri < 8; ri++){
                float a = As[(trow*8+ri)*17 + k];
                acc[ri][0] += a*bv.x; acc[ri][1] += a*bv.y;
                acc[ri][2] += a*bv.z; acc[ri][3] += a*bv.w;
            }
        }
        __syncthreads();
    }
    float4 b1v = *(const float4*)&bm1[tcol*4];
    #pragma unroll
    for (int ri = 0; ri < 8; ri++){
        float v0 = acc[ri][0]+b1v.x, v1 = acc[ri][1]+b1v.y;
        float v2 = acc[ri][2]+b1v.z, v3 = acc[ri][3]+b1v.w;
        float s1 = wsum(v0+v1+v2+v3);
        float s2 = wsum(v0*v0+v1*v1+v2*v2+v3*v3);
        float m  = s1 * (1.f/128.f);
        float var = s2 * (1.f/128.f) - m*m;
        float rs = rsqrtf(var + 1e-5f);
        int r = trow*8 + ri;
        float4 z = make_float4(fmaxf(0.f,(v0-m)*rs), fmaxf(0.f,(v1-m)*rs),
                               fmaxf(0.f,(v2-m)*rs), fmaxf(0.f,(v3-m)*rs));
        *(float4*)&Zs[r*132 + tcol*4] = z;
    }
    __syncthreads();

    float acc2[8][4];
    #pragma unroll
    for (int i = 0; i < 8; i++){ acc2[i][0]=0.f; acc2[i][1]=0.f; acc2[i][2]=0.f; acc2[i][3]=0.f; }
    for (int k0 = 0; k0 < 128; k0 += 16){
        #pragma unroll
        for (int i = 0; i < 8; i++){
            int lin = tid + 256*i;
            int k = lin >> 7, c = lin & 127;
            Bs[k*128+c] = Wm2[(k0+k)*128 + c];
        }
        __syncthreads();
        #pragma unroll
        for (int k = 0; k < 16; k++){
            float4 bv = *(const float4*)&Bs[k*128 + tcol*4];
            #pragma unroll
            for (int ri = 0; ri < 8; ri++){
                float a = Zs[(trow*8+ri)*132 + k0 + k];
                acc2[ri][0] += a*bv.x; acc2[ri][1] += a*bv.y;
                acc2[ri][2] += a*bv.z; acc2[ri][3] += a*bv.w;
            }
        }
        __syncthreads();
    }
    float4 b2v = *(const float4*)&bm2[tcol*4];
    #pragma unroll
    for (int ri = 0; ri < 8; ri++){
        int gr = row0 + trow*8 + ri;
        float v0 = acc2[ri][0]+b2v.x, v1 = acc2[ri][1]+b2v.y;
        float v2 = acc2[ri][2]+b2v.z, v3 = acc2[ri][3]+b2v.w;
        float s1 = wsum(v0+v1+v2+v3);
        float s2 = wsum(v0*v0+v1*v1+v2*v2+v3*v3);
        float m  = s1 * (1.f/128.f);
        float varu = (s2 - 128.f*m*m) * (1.f/127.f);
        float sd = sqrtf(varu);
        float o0 = n2n((v0-m)/sd), o1 = n2n((v1-m)/sd);
        float o2 = n2n((v2-m)/sd), o3 = n2n((v3-m)/sd);
        if (gr < Nn){
            *(float4*)&g_xa[gr*Hh + tcol*4] = make_float4(o0,o1,o2,o3);
            __half2 p0 = __floats2half2_rn(o0, o1);
            __half2 p1 = __floats2half2_rn(o2, o3);
            uint2 pw;
            pw.x = *(unsigned*)&p0; pw.y = *(unsigned*)&p1;
            *(uint2*)&g_xh[gr*Hh + tcol*4] = pw;
        }
    }
}

// ---------------- mirror descent (device, single thread) ----------------
__device__ void dev_md(int kiter){
    float w[Rr]; float l1 = 0.f;
    #pragma unroll
    for (int r = 0; r < Rr; r++){
        w[r] = (float)((g_node[r] - g_edge[r]) / (double)Nn);
        l1 += fabsf(w[r]);
        g_node[r] = 0.0; g_edge[r] = 0.0;
    }
    if (kiter == 0) g_clt = l1;
    float u[Rr];
    #pragma unroll
    for (int r = 0; r < Rr; r++) u[r] = g_u[r];
    float fi = l1 + 3.0f;          // ratio = 2*L2/L1 = 3
    bool ia = true;
    for (int t = 1; t <= 20 && ia; t++){
        float Tt = sqrtf(2.f*logf(5.f) / ((float)t * fi * fi));
        float uta[Rr]; float s = 0.f;
        #pragma unroll
        for (int r = 0; r < Rr; r++){ uta[r] = u[r]*expf(-Tt*(3.f*u[r] + w[r])); s += uta[r]; }
        float dif = 0.f;
        #pragma unroll
        for (int r = 0; r < Rr; r++){
            uta[r] /= s;
            float d = u[r] - uta[r];
            dif += d*d;
            u[r] = uta[r];
        }
        ia = (sqrtf(dif) >= 1e-3f);
    }
    #pragma unroll
    for (int r = 0; r < Rr; r++) g_u[r] = u[r];
    int still = (l1 / g_clt >= 0.3f) ? 1 : 0;
    g_still = still;
    g_act   = still;
}

// helper: fp16 row fetch -> 4 floats
__device__ __forceinline__ void ld_row(const __half* __restrict__ xh, int node, int lane,
                                       float& a, float& b, float& c, float& d){
    uint2 rv = *(const uint2*)(xh + (size_t)node*Hh + lane*4);
    float2 f0 = __half22float2(*(const __half2*)&rv.x);
    float2 f1 = __half22float2(*(const __half2*)&rv.y);
    a = f0.x; b = f0.y; c = f1.x; d = f1.y;
}

// ------- fused gather: per-relation msg (fp16) + TV + last-block mirror descent -------
__global__ void __launch_bounds__(256) k_gather(int kiter){
    if (!g_act) return;
    const __half* __restrict__ xh = g_xh;
    __shared__ double sE[Rr], sN[Rr];
    int tid = threadIdx.x;
    if (tid < Rr){ sE[tid] = 0.0; sN[tid] = 0.0; }
    __syncthreads();
    int n    = blockIdx.x*(blockDim.x>>5) + (tid>>5);
    int lane = tid & 31;
    if (n < Nn){
        float x0, x1, x2, x3;
        ld_row(xh, n, lane, x0, x1, x2, x3);
        float sq = wsum(x0*x0 + x1*x1 + x2*x2 + x3*x3);
        int e = g_rowptr[n];
        #pragma unroll
        for (int r = 0; r < Rr; r++){
            int len = g_degi[r*Nn + n];
            if (len > 0){
                float m0=0.f, m1=0.f, m2=0.f, m3=0.f, dt=0.f;
                int e1 = e + len;
                // unroll-by-4: batch independent gathers for MLP
                for (; e + 4 <= e1; e += 4){
                    int d0 = g_csr_dst[e],   d1 = g_csr_dst[e+1];
                    int d2 = g_csr_dst[e+2], d3 = g_csr_dst[e+3];
                    float ei0 = g_csr_edinv[e],   ei1 = g_csr_edinv[e+1];
                    float ei2 = g_csr_edinv[e+2], ei3 = g_csr_edinv[e+3];
                    float a0,a1,a2,a3, b0,b1,b2,b3, c0,c1,c2,c3, q0,q1,q2,q3;
                    ld_row(xh, d0, lane, a0,a1,a2,a3);
                    ld_row(xh, d1, lane, b0,b1,b2,b3);
                    ld_row(xh, d2, lane, c0,c1,c2,c3);
                    ld_row(xh, d3, lane, q0,q1,q2,q3);
                    m0 += a0+b0+c0+q0; m1 += a1+b1+c1+q1;
                    m2 += a2+b2+c2+q2; m3 += a3+b3+c3+q3;
                    dt += ei0*(x0*a0 + x1*a1 + x2*a2 + x3*a3);
                    dt += ei1*(x0*b0 + x1*b1 + x2*b2 + x3*b3);
                    dt += ei2*(x0*c0 + x1*c1 + x2*c2 + x3*c3);
                    dt += ei3*(x0*q0 + x1*q1 + x2*q2 + x3*q3);
                }
                for (; e < e1; e++){
                    int   d  = g_csr_dst[e];
                    float ei = g_csr_edinv[e];
                    float a0,a1,a2,a3;
                    ld_row(xh, d, lane, a0,a1,a2,a3);
                    m0 += a0; m1 += a1; m2 += a2; m3 += a3;
                    dt += ei*(x0*a0 + x1*a1 + x2*a2 + x3*a3);
                }
                float inv = 1.f/(float)len;
                __half2 p0 = __floats2half2_rn(m0*inv, m1*inv);
                __half2 p1 = __floats2half2_rn(m2*inv, m3*inv);
                uint2 pw; pw.x = *(unsigned*)&p0; pw.y = *(unsigned*)&p1;
                *(uint2*)(g_msgh + ((size_t)r*Nn + n)*Hh + lane*4) = pw;
                dt = wsum(dt);
                if (lane == 0){
                    atomicAdd(&sE[r], (double)dt);
                    atomicAdd(&sN[r], (double)sq);
                }
            }
        }
    }
    __syncthreads();
    if (tid < Rr){
        if (sE[tid] != 0.0) atomicAdd(&g_edge[tid], sE[tid]);
        if (sN[tid] != 0.0) atomicAdd(&g_node[tid], sN[tid]);
    }
    __threadfence();
    __syncthreads();
    if (tid == 0){
        unsigned t = atomicAdd(&g_barrier, 1u);
        if (t == gridDim.x - 1u){
            g_barrier = 0u;
            __threadfence();
            dev_md(kiter);
        }
    }
}

// ------- combine: x' = c1*x + c2 * sum_r u_r msg_r ; refresh fp16 mirror -------
__global__ void __launch_bounds__(256) k_combine(int parity){
    const float* __restrict__ xin  = parity ? g_xb : g_xa;
    float*       __restrict__ xout = parity ? g_xa : g_xb;
    __shared__ float su[Rr];
    int tid = threadIdx.x;
    if (tid < Rr) su[tid] = g_u[tid];
    __syncthreads();
    int still = g_still;
    int n    = blockIdx.x*(blockDim.x>>5) + (tid>>5);
    int lane = tid & 31;
    if (n >= Nn) return;
    float4 xv = *(const float4*)(xin + (size_t)n*Hh + lane*4);
    float4 o  = xv;
    if (still){
        float a0=0.f, a1=0.f, a2=0.f, a3=0.f;
        #pragma unroll
        for (int r = 0; r < Rr; r++){
            if (g_degi[r*Nn + n] > 0){
                uint2 rv = *(const uint2*)(g_msgh + ((size_t)r*Nn + n)*Hh + lane*4);
                float2 f0 = __half22float2(*(const __half2*)&rv.x);
                float2 f1 = __half22float2(*(const __half2*)&rv.y);
                float ur = su[r];
                a0 += ur*f0.x; a1 += ur*f0.y; a2 += ur*f1.x; a3 += ur*f1.y;
            }
        }
        const float c1 = 1.f/21.f, c2 = 20.f/21.f;
        o = make_float4(xv.x*c1 + c2*a0, xv.y*c1 + c2*a1,
                        xv.z*c1 + c2*a2, xv.w*c1 + c2*a3);
        *(float4*)(xout + (size_t)n*Hh + lane*4) = o;
        __half2 p0 = __floats2half2_rn(o.x, o.y);
        __half2 p1 = __floats2half2_rn(o.z, o.w);
        uint2 pw; pw.x = *(unsigned*)&p0; pw.y = *(unsigned*)&p1;
        *(uint2*)(g_xh + (size_t)n*Hh + lane*4) = pw;
    } else {
        *(float4*)(xout + (size_t)n*Hh + lane*4) = o;
    }
}

// ---------------- logits + output packing ----------------
__global__ void k_final(const float* __restrict__ Wout, const float* __restrict__ bout,
                        float* __restrict__ out, int out_size){
    __shared__ float sw[Hh*Cc];
    __shared__ float sb[Cc];
    int tid = threadIdx.x;
    for (int i = tid; i < Hh*Cc; i += blockDim.x) sw[i] = Wout[i];
    if (tid < Cc) sb[tid] = bout[tid];
    __syncthreads();
    int n    = blockIdx.x*(blockDim.x>>5) + (tid>>5);
    int lane = tid & 31;
    if (n >= Nn) return;
    float4 xv = *(const float4*)(g_xa + (size_t)n*Hh + lane*4);
    bool full = (out_size >= OFF_U + Rr);
    if (full) *(float4*)(out + OFF_X + (size_t)n*Hh + lane*4) = xv;
    float xs[4] = {xv.x, xv.y, xv.z, xv.w};
    float acc[Cc];
    #pragma unroll
    for (int c = 0; c < Cc; c++) acc[c] = 0.f;
    #pragma unroll
    for (int i = 0; i < 4; i++){
        const float* wr = &sw[(lane*4 + i)*Cc];
        #pragma unroll
        for (int c = 0; c < Cc; c++) acc[c] += xs[i]*wr[c];
    }
    #pragma unroll
    for (int c = 0; c < Cc; c++) acc[c] = wsum(acc[c]);
    if (lane == 0){
        #pragma unroll
        for (int c = 0; c < Cc; c++) out[(size_t)n*Cc + c] = acc[c] + sb[c];
    }
    if (full && blockIdx.x == 0 && tid < Rr) out[OFF_U + tid] = g_u[tid];
}

// ---------------- host launcher ----------------
extern "C" void kernel_launch(void* const* d_in, const int* in_sizes, int n_in,
                              void* d_out, int out_size){
    const float* feat0 = (const float*)d_in[0];
    const float* feat1 = (const float*)d_in[1];
    const float* W0   = (const float*)d_in[2];  const float* b0   = (const float*)d_in[3];
    const float* W1   = (const float*)d_in[4];  const float* b1   = (const float*)d_in[5];
    const float* Wm1  = (const float*)d_in[6];  const float* bm1  = (const float*)d_in[7];
    const float* Wm2  = (const float*)d_in[8];  const float* bm2  = (const float*)d_in[9];
    const float* Wout = (const float*)d_in[10]; const float* bout = (const float*)d_in[11];
    const int*   src  = (const int*)d_in[12];
    const int*   dst  = (const int*)d_in[13];
    const int*   rel  = (const int*)d_in[14];
    float* out = (float*)d_out;

    const int EB = (Ee + 255)/256;          // 2344
    const int NB_SCAN = (Nn + 1023)/1024;   // 30

    k_init<<<256, 256>>>();
    k_count<<<EB, 256>>>(src, rel);

    k_gemm<<<(NN0+63)/64, 256>>>(feat0, 256, NN0, 0,   W0, b0, 256);
    k_gemm<<<(NN1+63)/64, 256>>>(feat1, 128, NN1, NN0, W1, b1, 128);
    k_mlp2<<<(Nn+63)/64, 256>>>(Wm1, bm1, Wm2, bm2);

    k_scan1<<<NB_SCAN, 1024>>>();
    k_scan2<<<1, 32>>>(NB_SCAN);
    k_scan3<<<(Nn+255)/256, 256>>>();
    k_cursor2<<<(Nn+255)/256, 256>>>();
    k_scatter2<<<EB, 256>>>(src, dst, rel);

    const int NW = (Nn + 7)/8;   // warp per node -> 3750 blocks
    for (int k = 0; k < 8; k++){
        k_gather<<<NW, 256>>>(k);
        k_combine<<<NW, 256>>>(k & 1);
    }
    k_final<<<NW, 256>>>(Wout, bout, out, out_size);
}

// round 5
// speedup vs baseline: 1.0648x; 1.0648x over previous
#include <cuda_runtime.h>
#include <cuda_fp16.h>
#include <math.h>

#define Nn 30000
#define NN0 18000
#define NN1 12000
#define Rr 5
#define Ee 600000
#define Hh 128
#define Cc 8
#define OFF_X (Nn*Cc)            /* 240000   */
#define OFF_U (OFF_X + Nn*Hh)    /* 4080000  */

#define GRID 592                  /* 148 SMs x 4 co-resident blocks */
#define BLK  256
#define WPB  (BLK/32)
#define NWARPS (GRID*WPB)

// ---------------- device scratch (static, no allocation) ----------------
__device__ float  g_h [Nn*Hh];
__device__ float  g_xa[Nn*Hh];                 // fp32 x, updated in place
__device__ __half g_xh[Nn*Hh];                 // fp16 mirror of current x
__device__ __half g_msgh[(size_t)Rr*Nn*Hh];    // per-relation messages fp16
__device__ int    g_degi[Rr*Nn];
__device__ int    g_cnt[Nn];
__device__ int    g_rowptr[Nn+1];
__device__ int    g_cur2[Rr*Nn];
__device__ int    g_bsums[64];
__device__ int    g_csr_dst[Ee];
__device__ float  g_csr_edinv[Ee];
__device__ double g_node[Rr];
__device__ double g_edge[Rr];
__device__ float  g_u[Rr];
__device__ float  g_clt;
__device__ int    g_act;
__device__ int    g_still;
__device__ unsigned g_bcount;
__device__ volatile unsigned g_bsense;

__device__ __forceinline__ float wsum(float v){
    #pragma unroll
    for (int o = 16; o; o >>= 1) v += __shfl_xor_sync(0xffffffffu, v, o);
    return v;
}
__device__ __forceinline__ float n2n(float v){
    if (isnan(v)) return 0.f;
    if (isinf(v)) return v > 0.f ? 3.4028234663852886e38f : -3.4028234663852886e38f;
    return v;
}

// ---------------- init / graph preprocessing ----------------
__global__ void k_init(){
    int i = blockIdx.x*blockDim.x + threadIdx.x;
    int st = gridDim.x*blockDim.x;
    for (int j = i; j < Rr*Nn; j += st) g_degi[j] = 0;
    for (int j = i; j < Nn;    j += st) g_cnt[j]  = 0;
    if (i < Rr) { g_node[i] = 0.0; g_edge[i] = 0.0; g_u[i] = 0.2f; }
    if (i == 0) { g_act = 1; g_still = 1; g_bcount = 0u; g_bsense = 0u; }
}

__global__ void k_count(const int* __restrict__ src, const int* __restrict__ rel){
    int i = blockIdx.x*blockDim.x + threadIdx.x;
    if (i < Ee) {
        atomicAdd(&g_degi[rel[i]*Nn + src[i]], 1);
        atomicAdd(&g_cnt[src[i]], 1);
    }
}

__global__ void k_scan1(){
    __shared__ int s[1024];
    int i = blockIdx.x*1024 + threadIdx.x;
    int v = (i < Nn) ? g_cnt[i] : 0;
    s[threadIdx.x] = v;
    __syncthreads();
    for (int off = 1; off < 1024; off <<= 1){
        int t = 0;
        if (threadIdx.x >= off) t = s[threadIdx.x - off];
        __syncthreads();
        if (threadIdx.x >= off) s[threadIdx.x] += t;
        __syncthreads();
    }
    if (i < Nn) g_rowptr[i] = s[threadIdx.x] - v;
    if (threadIdx.x == 1023) g_bsums[blockIdx.x] = s[1023];
}

__global__ void k_scan2(int nb){
    if (threadIdx.x == 0){
        int run = 0;
        for (int b = 0; b < nb; b++){ int t = g_bsums[b]; g_bsums[b] = run; run += t; }
    }
}

__global__ void k_scan3(){
    int i = blockIdx.x*blockDim.x + threadIdx.x;
    if (i < Nn) g_rowptr[i] = g_rowptr[i] + g_bsums[i >> 10];
    if (i == 0) g_rowptr[Nn] = Ee;
}

__global__ void k_cursor2(){
    int s = blockIdx.x*blockDim.x + threadIdx.x;
    if (s >= Nn) return;
    int base = g_rowptr[s];
    #pragma unroll
    for (int r = 0; r < Rr; r++){
        g_cur2[r*Nn + s] = base;
        base += g_degi[r*Nn + s];
    }
}

__global__ void k_scatter2(const int* __restrict__ src, const int* __restrict__ dst,
                           const int* __restrict__ rel){
    int i = blockIdx.x*blockDim.x + threadIdx.x;
    if (i >= Ee) return;
    int s = src[i], r = rel[i], d = dst[i];
    int pos = atomicAdd(&g_cur2[r*Nn + s], 1);
    int degs = g_degi[r*Nn + s];
    int degd = g_degi[r*Nn + d];
    float ei = (1.f/sqrtf((float)degs)) * (degd > 0 ? 1.f/sqrtf((float)degd) : 0.f);
    g_csr_dst[pos]   = d;
    g_csr_edinv[pos] = ei;
}

// ---------------- stage A GEMM: h = feat @ W + b ----------------
__global__ void __launch_bounds__(256) k_gemm(const float* __restrict__ A, int lda, int nrows,
                                              int rowbase,
                                              const float* __restrict__ W,
                                              const float* __restrict__ bias, int K){
    __shared__ float As[64*17];
    __shared__ float Bs[16*128];
    int tid  = threadIdx.x;
    int tcol = tid & 31, trow = tid >> 5;
    int row0 = blockIdx.x * 64;
    float acc[8][4];
    #pragma unroll
    for (int i = 0; i < 8; i++){ acc[i][0]=0.f; acc[i][1]=0.f; acc[i][2]=0.f; acc[i][3]=0.f; }

    for (int k0 = 0; k0 < K; k0 += 16){
        #pragma unroll
        for (int i = 0; i < 4; i++){
            int lin = tid + 256*i;
            int r = lin >> 4, k = lin & 15;
            int gr = row0 + r;
            As[r*17+k] = (gr < nrows) ? A[gr*lda + k0 + k] : 0.f;
        }
        #pragma unroll
        for (int i = 0; i < 8; i++){
            int lin = tid + 256*i;
            int k = lin >> 7, c = lin & 127;
            Bs[k*128+c] = W[(k0+k)*128 + c];
        }
        __syncthreads();
        #pragma unroll
        for (int k = 0; k < 16; k++){
            float4 bv = *(const float4*)&Bs[k*128 + tcol*4];
            #pragma unroll
            for (int ri = 0; ri < 8; ri++){
                float a = As[(trow*8+ri)*17 + k];
                acc[ri][0] += a*bv.x; acc[ri][1] += a*bv.y;
                acc[ri][2] += a*bv.z; acc[ri][3] += a*bv.w;
            }
        }
        __syncthreads();
    }
    float4 bv = *(const float4*)&bias[tcol*4];
    #pragma unroll
    for (int ri = 0; ri < 8; ri++){
        int gr = row0 + trow*8 + ri;
        if (gr < nrows){
            float4 o = make_float4(acc[ri][0]+bv.x, acc[ri][1]+bv.y,
                                   acc[ri][2]+bv.z, acc[ri][3]+bv.w);
            *(float4*)&g_h[(rowbase+gr)*Hh + tcol*4] = o;
        }
    }
}

// ---------------- stage B: LN(h@Wm1+b)->relu -> @Wm2+b -> standardize ----------------
__global__ void __launch_bounds__(256) k_mlp2(const float* __restrict__ Wm1, const float* __restrict__ bm1,
                                              const float* __restrict__ Wm2, const float* __restrict__ bm2){
    __shared__ float As[64*17];
    __shared__ float Bs[16*128];
    __shared__ float Zs[64*132];
    int tid  = threadIdx.x;
    int tcol = tid & 31, trow = tid >> 5;
    int row0 = blockIdx.x * 64;
    float acc[8][4];
    #pragma unroll
    for (int i = 0; i < 8; i++){ acc[i][0]=0.f; acc[i][1]=0.f; acc[i][2]=0.f; acc[i][3]=0.f; }

    for (int k0 = 0; k0 < 128; k0 += 16){
        #pragma unroll
        for (int i = 0; i < 4; i++){
            int lin = tid + 256*i;
            int r = lin >> 4, k = lin & 15;
            int gr = row0 + r;
            As[r*17+k] = (gr < Nn) ? g_h[gr*Hh + k0 + k] : 0.f;
        }
        #pragma unroll
        for (int i = 0; i < 8; i++){
            int lin = tid + 256*i;
            int k = lin >> 7, c = lin & 127;
            Bs[k*128+c] = Wm1[(k0+k)*128 + c];
        }
        __syncthreads();
        #pragma unroll
        for (int k = 0; k < 16; k++){
            float4 bv = *(const float4*)&Bs[k*128 + tcol*4];
            #pragma unroll
            for (int ri = 0; ri < 8; ri++){
                float a = As[(trow*8+ri)*17 + k];
                acc[ri][0] += a*bv.x; acc[ri][1] += a*bv.y;
                acc[ri][2] += a*bv.z; acc[ri][3] += a*bv.w;
            }
        }
        __syncthreads();
    }
    float4 b1v = *(const float4*)&bm1[tcol*4];
    #pragma unroll
    for (int ri = 0; ri < 8; ri++){
        float v0 = acc[ri][0]+b1v.x, v1 = acc[ri][1]+b1v.y;
        float v2 = acc[ri][2]+b1v.z, v3 = acc[ri][3]+b1v.w;
        float s1 = wsum(v0+v1+v2+v3);
        float s2 = wsum(v0*v0+v1*v1+v2*v2+v3*v3);
        float m  = s1 * (1.f/128.f);
        float var = s2 * (1.f/128.f) - m*m;
        float rs = rsqrtf(var + 1e-5f);
        int r = trow*8 + ri;
        float4 z = make_float4(fmaxf(0.f,(v0-m)*rs), fmaxf(0.f,(v1-m)*rs),
                               fmaxf(0.f,(v2-m)*rs), fmaxf(0.f,(v3-m)*rs));
        *(float4*)&Zs[r*132 + tcol*4] = z;
    }
    __syncthreads();

    float acc2[8][4];
    #pragma unroll
    for (int i = 0; i < 8; i++){ acc2[i][0]=0.f; acc2[i][1]=0.f; acc2[i][2]=0.f; acc2[i][3]=0.f; }
    for (int k0 = 0; k0 < 128; k0 += 16){
        #pragma unroll
        for (int i = 0; i < 8; i++){
            int lin = tid + 256*i;
            int k = lin >> 7, c = lin & 127;
            Bs[k*128+c] = Wm2[(k0+k)*128 + c];
        }
        __syncthreads();
        #pragma unroll
        for (int k = 0; k < 16; k++){
            float4 bv = *(const float4*)&Bs[k*128 + tcol*4];
            #pragma unroll
            for (int ri = 0; ri < 8; ri++){
                float a = Zs[(trow*8+ri)*132 + k0 + k];
                acc2[ri][0] += a*bv.x; acc2[ri][1] += a*bv.y;
                acc2[ri][2] += a*bv.z; acc2[ri][3] += a*bv.w;
            }
        }
        __syncthreads();
    }
    float4 b2v = *(const float4*)&bm2[tcol*4];
    #pragma unroll
    for (int ri = 0; ri < 8; ri++){
        int gr = row0 + trow*8 + ri;
        float v0 = acc2[ri][0]+b2v.x, v1 = acc2[ri][1]+b2v.y;
        float v2 = acc2[ri][2]+b2v.z, v3 = acc2[ri][3]+b2v.w;
        float s1 = wsum(v0+v1+v2+v3);
        float s2 = wsum(v0*v0+v1*v1+v2*v2+v3*v3);
        float m  = s1 * (1.f/128.f);
        float varu = (s2 - 128.f*m*m) * (1.f/127.f);
        float sd = sqrtf(varu);
        float o0 = n2n((v0-m)/sd), o1 = n2n((v1-m)/sd);
        float o2 = n2n((v2-m)/sd), o3 = n2n((v3-m)/sd);
        if (gr < Nn){
            *(float4*)&g_xa[gr*Hh + tcol*4] = make_float4(o0,o1,o2,o3);
            __half2 p0 = __floats2half2_rn(o0, o1);
            __half2 p1 = __floats2half2_rn(o2, o3);
            uint2 pw;
            pw.x = *(unsigned*)&p0; pw.y = *(unsigned*)&p1;
            *(uint2*)&g_xh[gr*Hh + tcol*4] = pw;
        }
    }
}

// ---------------- mirror descent (runs inside grid barrier; volatile L2 access) ----------------
__device__ void dev_md(int kiter){
    float w[Rr]; float l1 = 0.f;
    #pragma unroll
    for (int r = 0; r < Rr; r++){
        double nv = *(volatile double*)&g_node[r];
        double ev = *(volatile double*)&g_edge[r];
        w[r] = (float)((nv - ev) / (double)Nn);
        l1 += fabsf(w[r]);
        *(volatile double*)&g_node[r] = 0.0;
        *(volatile double*)&g_edge[r] = 0.0;
    }
    float clt;
    if (kiter == 0){ clt = l1; *(volatile float*)&g_clt = l1; }
    else clt = *(volatile float*)&g_clt;
    float u[Rr];
    #pragma unroll
    for (int r = 0; r < Rr; r++) u[r] = *(volatile float*)&g_u[r];
    float fi = l1 + 3.0f;          // ratio = 2*L2/L1 = 3
    bool ia = true;
    for (int t = 1; t <= 20 && ia; t++){
        float Tt = sqrtf(2.f*logf(5.f) / ((float)t * fi * fi));
        float uta[Rr]; float s = 0.f;
        #pragma unroll
        for (int r = 0; r < Rr; r++){ uta[r] = u[r]*expf(-Tt*(3.f*u[r] + w[r])); s += uta[r]; }
        float dif = 0.f;
        #pragma unroll
        for (int r = 0; r < Rr; r++){
            uta[r] /= s;
            float d = u[r] - uta[r];
            dif += d*d;
            u[r] = uta[r];
        }
        ia = (sqrtf(dif) >= 1e-3f);
    }
    #pragma unroll
    for (int r = 0; r < Rr; r++) *(volatile float*)&g_u[r] = u[r];
    int still = (l1 / clt >= 0.3f) ? 1 : 0;
    *(volatile int*)&g_still = still;
    *(volatile int*)&g_act   = still;
}

// ---------------- grid barrier (sense-reversing); last block may run md ----------------
__device__ __forceinline__ void gbar(int run_md, int kiter){
    __syncthreads();
    if (threadIdx.x == 0){
        unsigned s = g_bsense;
        __threadfence();
        unsigned a = atomicAdd(&g_bcount, 1u);
        if (a == (unsigned)(GRID - 1)){
            if (run_md) dev_md(kiter);
            g_bcount = 0u;
            __threadfence();
            g_bsense = s ^ 1u;
        } else {
            while (g_bsense == s) __nanosleep(64);
            __threadfence();
        }
    }
    __syncthreads();
}

// helper: fp16 row fetch (L2-only, cross-SM coherent) -> 4 floats
__device__ __forceinline__ void ld_row_cg(const __half* __restrict__ xh, int node, int lane,
                                          float& a, float& b, float& c, float& d){
    unsigned long long rv = __ldcg((const unsigned long long*)(xh + (size_t)node*Hh + lane*4));
    unsigned lo = (unsigned)rv, hi = (unsigned)(rv >> 32);
    float2 f0 = __half22float2(*(__half2*)&lo);
    float2 f1 = __half22float2(*(__half2*)&hi);
    a = f0.x; b = f0.y; c = f1.x; d = f1.y;
}

// ---------------- persistent loop: 8 x (gather -> md -> combine) + final output ----------------
__global__ void __launch_bounds__(BLK, 4) k_loop(const float* __restrict__ Wout,
                                                 const float* __restrict__ bout,
                                                 float* __restrict__ out, int out_size){
    __shared__ double sE[Rr], sN[Rr];
    __shared__ float  su[Rr];
    __shared__ float  swt[Hh*Cc];
    __shared__ float  sbv[Cc];
    int tid  = threadIdx.x;
    int lane = tid & 31;
    int gwarp = blockIdx.x*WPB + (tid >> 5);

    for (int k = 0; k < 8; k++){
        int act = *(volatile int*)&g_act;
        if (act){
            if (tid < Rr){ sE[tid] = 0.0; sN[tid] = 0.0; }
            __syncthreads();
            for (int n = gwarp; n < Nn; n += NWARPS){
                float x0, x1, x2, x3;
                {   // own row: written by this same warp last combine -> L1-safe
                    uint2 rv = *(const uint2*)(g_xh + (size_t)n*Hh + lane*4);
                    float2 f0 = __half22float2(*(const __half2*)&rv.x);
                    float2 f1 = __half22float2(*(const __half2*)&rv.y);
                    x0 = f0.x; x1 = f0.y; x2 = f1.x; x3 = f1.y;
                }
                float sq = wsum(x0*x0 + x1*x1 + x2*x2 + x3*x3);
                int e = g_rowptr[n];
                #pragma unroll
                for (int r = 0; r < Rr; r++){
                    int len = g_degi[r*Nn + n];
                    if (len > 0){
                        float m0=0.f, m1=0.f, m2=0.f, m3=0.f, dt=0.f;
                        int e1 = e + len;
                        for (; e + 4 <= e1; e += 4){
                            int d0 = g_csr_dst[e],   d1 = g_csr_dst[e+1];
                            int d2 = g_csr_dst[e+2], d3 = g_csr_dst[e+3];
                            float ei0 = g_csr_edinv[e],   ei1 = g_csr_edinv[e+1];
                            float ei2 = g_csr_edinv[e+2], ei3 = g_csr_edinv[e+3];
                            float a0,a1,a2,a3, b0,b1,b2,b3, c0,c1,c2,c3, q0,q1,q2,q3;
                            ld_row_cg(g_xh, d0, lane, a0,a1,a2,a3);
                            ld_row_cg(g_xh, d1, lane, b0,b1,b2,b3);
                            ld_row_cg(g_xh, d2, lane, c0,c1,c2,c3);
                            ld_row_cg(g_xh, d3, lane, q0,q1,q2,q3);
                            m0 += a0+b0+c0+q0; m1 += a1+b1+c1+q1;
                            m2 += a2+b2+c2+q2; m3 += a3+b3+c3+q3;
                            dt += ei0*(x0*a0 + x1*a1 + x2*a2 + x3*a3);
                            dt += ei1*(x0*b0 + x1*b1 + x2*b2 + x3*b3);
                            dt += ei2*(x0*c0 + x1*c1 + x2*c2 + x3*c3);
                            dt += ei3*(x0*q0 + x1*q1 + x2*q2 + x3*q3);
                        }
                        for (; e < e1; e++){
                            int   d  = g_csr_dst[e];
                            float ei = g_csr_edinv[e];
                            float a0,a1,a2,a3;
                            ld_row_cg(g_xh, d, lane, a0,a1,a2,a3);
                            m0 += a0; m1 += a1; m2 += a2; m3 += a3;
                            dt += ei*(x0*a0 + x1*a1 + x2*a2 + x3*a3);
                        }
                        float inv = 1.f/(float)len;
                        __half2 p0 = __floats2half2_rn(m0*inv, m1*inv);
                        __half2 p1 = __floats2half2_rn(m2*inv, m3*inv);
                        uint2 pw; pw.x = *(unsigned*)&p0; pw.y = *(unsigned*)&p1;
                        *(uint2*)(g_msgh + ((size_t)r*Nn + n)*Hh + lane*4) = pw;
                        dt = wsum(dt);
                        if (lane == 0){
                            atomicAdd(&sE[r], (double)dt);
                            atomicAdd(&sN[r], (double)sq);
                        }
                    }
                }
            }
            __syncthreads();
            if (tid < Rr){
                if (sE[tid] != 0.0) atomicAdd(&g_edge[tid], sE[tid]);
                if (sN[tid] != 0.0) atomicAdd(&g_node[tid], sN[tid]);
            }
        }
        gbar(act, k);                       // last-arriving block runs mirror descent

        int still = *(volatile int*)&g_still;
        if (still){
            if (tid < Rr) su[tid] = *(volatile float*)&g_u[tid];
            __syncthreads();
            const float c1 = 1.f/21.f, c2 = 20.f/21.f;
            for (int n = gwarp; n < Nn; n += NWARPS){
                float4 xv = *(const float4*)(g_xa + (size_t)n*Hh + lane*4);
                float a0=0.f, a1=0.f, a2=0.f, a3=0.f;
                #pragma unroll
                for (int r = 0; r < Rr; r++){
                    if (g_degi[r*Nn + n] > 0){
                        uint2 rv = *(const uint2*)(g_msgh + ((size_t)r*Nn + n)*Hh + lane*4);
                        float2 f0 = __half22float2(*(const __half2*)&rv.x);
                        float2 f1 = __half22float2(*(const __half2*)&rv.y);
                        float ur = su[r];
                        a0 += ur*f0.x; a1 += ur*f0.y; a2 += ur*f1.x; a3 += ur*f1.y;
                    }
                }
                float4 o = make_float4(xv.x*c1 + c2*a0, xv.y*c1 + c2*a1,
                                       xv.z*c1 + c2*a2, xv.w*c1 + c2*a3);
                *(float4*)(g_xa + (size_t)n*Hh + lane*4) = o;
                __half2 p0 = __floats2half2_rn(o.x, o.y);
                __half2 p1 = __floats2half2_rn(o.z, o.w);
                uint2 pw; pw.x = *(unsigned*)&p0; pw.y = *(unsigned*)&p1;
                *(uint2*)(g_xh + (size_t)n*Hh + lane*4) = pw;
            }
        }
        gbar(0, 0);
    }

    // ---------- final: logits + output packing ----------
    for (int i = tid; i < Hh*Cc; i += BLK) swt[i] = Wout[i];
    if (tid < Cc) sbv[tid] = bout[tid];
    __syncthreads();
    bool full = (out_size >= OFF_U + Rr);
    for (int n = gwarp; n < Nn; n += NWARPS){
        float4 xv = *(const float4*)(g_xa + (size_t)n*Hh + lane*4);
        if (full) *(float4*)(out + OFF_X + (size_t)n*Hh + lane*4) = xv;
        float xs[4] = {xv.x, xv.y, xv.z, xv.w};
        float acc[Cc];
        #pragma unroll
        for (int c = 0; c < Cc; c++) acc[c] = 0.f;
        #pragma unroll
        for (int i = 0; i < 4; i++){
            const float* wr = &swt[(lane*4 + i)*Cc];
            #pragma unroll
            for (int c = 0; c < Cc; c++) acc[c] += xs[i]*wr[c];
        }
        #pragma unroll
        for (int c = 0; c < Cc; c++) acc[c] = wsum(acc[c]);
        if (lane == 0){
            #pragma unroll
            for (int c = 0; c < Cc; c++) out[(size_t)n*Cc + c] = acc[c] + sbv[c];
        }
    }
    if (full && blockIdx.x == 0 && tid < Rr) out[OFF_U + tid] = *(volatile float*)&g_u[tid];
}

// ---------------- host launcher ----------------
extern "C" void kernel_launch(void* const* d_in, const int* in_sizes, int n_in,
                              void* d_out, int out_size){
    const float* feat0 = (const float*)d_in[0];
    const float* feat1 = (const float*)d_in[1];
    const float* W0   = (const float*)d_in[2];  const float* b0   = (const float*)d_in[3];
    const float* W1   = (const float*)d_in[4];  const float* b1   = (const float*)d_in[5];
    const float* Wm1  = (const float*)d_in[6];  const float* bm1  = (const float*)d_in[7];
    const float* Wm2  = (const float*)d_in[8];  const float* bm2  = (const float*)d_in[9];
    const float* Wout = (const float*)d_in[10]; const float* bout = (const float*)d_in[11];
    const int*   src  = (const int*)d_in[12];
    const int*   dst  = (const int*)d_in[13];
    const int*   rel  = (const int*)d_in[14];
    float* out = (float*)d_out;

    const int EB = (Ee + 255)/256;          // 2344
    const int NB_SCAN = (Nn + 1023)/1024;   // 30

    k_init<<<256, 256>>>();
    k_count<<<EB, 256>>>(src, rel);

    k_gemm<<<(NN0+63)/64, 256>>>(feat0, 256, NN0, 0,   W0, b0, 256);
    k_gemm<<<(NN1+63)/64, 256>>>(feat1, 128, NN1, NN0, W1, b1, 128);
    k_mlp2<<<(Nn+63)/64, 256>>>(Wm1, bm1, Wm2, bm2);

    k_scan1<<<NB_SCAN, 1024>>>();
    k_scan2<<<1, 32>>>(NB_SCAN);
    k_scan3<<<(Nn+255)/256, 256>>>();
    k_cursor2<<<(Nn+255)/256, 256>>>();
    k_scatter2<<<EB, 256>>>(src, dst, rel);

    k_loop<<<GRID, BLK>>>(Wout, bout, out, out_size);
}